// round 9
// baseline (speedup 1.0000x reference)
#include <cuda_runtime.h>
#include <cuda_fp16.h>
#include <cstdint>

// ----------------------------------------------------------------------------
// Problem constants
// ----------------------------------------------------------------------------
#define M_TOTAL 8192   // B*S
#define K_TOTAL 4096   // IN
#define N_TOTAL 4096   // OUT

#define CTA_M 128
#define CTA_N 256
#define K_TILE 128
#define NK     (K_TOTAL / K_TILE)   // 32
#define STAGES 2
#define NTH    256

// Static device scratch (allowed; no dynamic allocation anywhere)
__device__ __align__(128) __half g_xh[(size_t)M_TOTAL * K_TOTAL];   // fp16 x, 64MB
__device__ __align__(128) __half g_wh[(size_t)K_TOTAL * N_TOTAL];   // fp16 q (0..15 exact), 32MB
__device__ float g_rowsum[M_TOTAL];                                  // exact fp32 row sums

// ----------------------------------------------------------------------------
// Helpers (arch-agnostic ISA only: cp.async, ldmatrix, mma.sync)
// ----------------------------------------------------------------------------
__device__ __forceinline__ uint32_t smem_u32(const void* p) {
    uint32_t a;
    asm("{ .reg .u64 t; cvta.to.shared.u64 t, %1; cvt.u32.u64 %0, t; }"
        : "=r"(a) : "l"(p));
    return a;
}

__device__ __forceinline__ void cp16(uint32_t dst, const void* src) {
    asm volatile("cp.async.cg.shared.global [%0], [%1], 16;" :: "r"(dst), "l"(src));
}

__device__ __forceinline__ void ldsm4(uint32_t* r, uint32_t a) {
    asm volatile("ldmatrix.sync.aligned.m8n8.x4.shared.b16 {%0,%1,%2,%3}, [%4];"
        : "=r"(r[0]), "=r"(r[1]), "=r"(r[2]), "=r"(r[3]) : "r"(a));
}

__device__ __forceinline__ void ldsm4t(uint32_t* r, uint32_t a) {
    asm volatile("ldmatrix.sync.aligned.m8n8.x4.trans.shared.b16 {%0,%1,%2,%3}, [%4];"
        : "=r"(r[0]), "=r"(r[1]), "=r"(r[2]), "=r"(r[3]) : "r"(a));
}

__device__ __forceinline__ void mma16816(float* c, const uint32_t* a,
                                         uint32_t b0, uint32_t b1) {
    asm volatile("mma.sync.aligned.m16n8k16.row.col.f32.f16.f16.f32 "
        "{%0,%1,%2,%3}, {%4,%5,%6,%7}, {%8,%9}, {%0,%1,%2,%3};"
        : "+f"(c[0]), "+f"(c[1]), "+f"(c[2]), "+f"(c[3])
        : "r"(a[0]), "r"(a[1]), "r"(a[2]), "r"(a[3]), "r"(b0), "r"(b1));
}

__device__ __forceinline__ void stcs2(float* p, float2 v) {
    asm volatile("st.global.cs.v2.f32 [%0], {%1, %2};" :: "l"(p), "f"(v.x), "f"(v.y) : "memory");
}

// ----------------------------------------------------------------------------
// Merged prepass:
//   blocks [0, M_TOTAL)          : x fp32 -> fp16 + exact fp32 row sums
//   blocks [M_TOTAL, M_TOTAL+1024): unpack int4 -> fp16 (0..15 exact), 16B stores
// ----------------------------------------------------------------------------
__global__ void __launch_bounds__(256) prepass_kernel(const float* __restrict__ x,
                                                      const int* __restrict__ qw) {
    if (blockIdx.x < M_TOTAL) {
        const int m = blockIdx.x;
        const float4* xr = reinterpret_cast<const float4*>(x + (size_t)m * K_TOTAL);
        __half2* xo = reinterpret_cast<__half2*>(g_xh + (size_t)m * K_TOTAL);
        float s = 0.f;
#pragma unroll
        for (int i = threadIdx.x; i < K_TOTAL / 4; i += 256) {
            float4 v = xr[i];
            s += (v.x + v.y) + (v.z + v.w);
            xo[2 * i]     = __floats2half2_rn(v.x, v.y);
            xo[2 * i + 1] = __floats2half2_rn(v.z, v.w);
        }
#pragma unroll
        for (int o = 16; o; o >>= 1) s += __shfl_xor_sync(0xFFFFFFFFu, s, o);
        __shared__ float ws[8];
        if ((threadIdx.x & 31) == 0) ws[threadIdx.x >> 5] = s;
        __syncthreads();
        if (threadIdx.x == 0) {
            float t = 0.f;
#pragma unroll
            for (int i = 0; i < 8; i++) t += ws[i];
            g_rowsum[m] = t;
        }
    } else {
        const int idx = (blockIdx.x - M_TOTAL) * 256 + threadIdx.x; // 0..(K/8)*(N/8)-1
        const int p  = idx >> 9;                          // packed row (N/8 = 512 groups)
        const int n8 = (idx & 511) * 8;
        const uint4* q = reinterpret_cast<const uint4*>(qw + (size_t)p * N_TOTAL + n8);
        uint4 w0 = q[0], w1 = q[1];
        uint32_t w[8] = {w0.x, w0.y, w0.z, w0.w, w1.x, w1.y, w1.z, w1.w};
        const uint32_t MAGIC = 0x64006400u;               // fp16x2 (1024,1024)
        const __half2 mh = *reinterpret_cast<const __half2*>(&MAGIC);
#pragma unroll
        for (int j = 0; j < 8; j++) {
            uint32_t o[4];
#pragma unroll
            for (int t = 0; t < 4; t++) {
                uint32_t lo = (w[2 * t]     >> (4 * j)) & 0xFu;
                uint32_t hi = (w[2 * t + 1] >> (4 * j)) & 0xFu;
                uint32_t u = lo | (hi << 16) | MAGIC;
                __half2 h = __hsub2(*reinterpret_cast<const __half2*>(&u), mh);
                o[t] = *reinterpret_cast<uint32_t*>(&h);
            }
            *reinterpret_cast<uint4*>(g_wh + (size_t)(p * 8 + j) * N_TOTAL + n8) =
                make_uint4(o[0], o[1], o[2], o[3]);
        }
    }
}

// ----------------------------------------------------------------------------
// GEMM: D[m][n] = sum_k xh[m][k] * wh[k][n]   (fp16 inputs, fp32 accum)
// CTA 128x256, warp grid 2(M) x 4(N), warp tile 64x64, K_TILE=128, 2 stages.
// Early mid-iteration wait (ks=3) + cross-tile fragment prefetch hide boundaries.
// Epilogue: out = sc*D - zz*rowsum + bias
// ----------------------------------------------------------------------------
// SMEM layout (relative to 1024-aligned base)
#define OFF_SC 0
#define OFF_ZZ 1024
#define OFF_BB 2048
#define OFF_A  3072                 // 2 x 32KB: [128 rows m][128 halves k], 256B rows
#define A_BYTES 32768
#define OFF_B  (OFF_A + STAGES * A_BYTES)   // 2 x 64KB: [128 rows k][256 halves n], 512B rows
#define B_BYTES 65536
#define SMEM_USED (OFF_B + STAGES * B_BYTES)
#define SMEM_BYTES (SMEM_USED + 1024)

#define KCH (K_TILE / 16)    // 8 k-chunks per tile
#define WAIT_KS 3            // barrier position: 4 chunks of skew-absorbing work after

__device__ __forceinline__ void load_tile(uint32_t abase, int stage,
                                          const __half* __restrict__ asrc,
                                          const __half* __restrict__ bsrc,
                                          int tid) {
    // A tile: rows m (128), cols k (128 halves = 256B). swz within 128B half.
    const uint32_t a_s = abase + OFF_A + stage * A_BYTES;
#pragma unroll
    for (int it = 0; it < 2048 / NTH; it++) {
        int i = tid + it * NTH;
        int r = i >> 4, c = i & 15;
        uint32_t off = (uint32_t)(r * 256 + ((c * 16) ^ ((r & 7) << 4)));
        cp16(a_s + off, asrc + (size_t)r * K_TOTAL + c * 8);
    }
    // B tile: rows k (128), cols n (256 halves = 512B). swz within 128B region.
    const uint32_t b_s = abase + OFF_B + stage * B_BYTES;
#pragma unroll
    for (int it = 0; it < 4096 / NTH; it++) {
        int i = tid + it * NTH;
        int r = i >> 5, c = i & 31;
        uint32_t off = (uint32_t)(r * 512 + ((c * 16) ^ ((r & 7) << 4)));
        cp16(b_s + off, bsrc + (size_t)r * N_TOTAL + c * 8);
    }
}

__global__ void __launch_bounds__(NTH, 1)
gemm_kernel(const float* __restrict__ sc, const float* __restrict__ zz,
            const float* __restrict__ bb, float* __restrict__ out) {
    extern __shared__ char dsm[];
    const uint32_t raw = smem_u32(dsm);
    const uint32_t abase = (raw + 1023u) & ~1023u;
    char* smp = dsm + (abase - raw);

    const int tid = threadIdx.x;
    const int lane = tid & 31;
    const int wid = tid >> 5;
    const int warp_m = wid & 1;        // 2 warps over M (64 rows each)
    const int warp_n = wid >> 1;       // 4 warps over N (64 cols each)
    const int nt = blockIdx.x & 15;    // N fastest -> B stays L2-resident
    const int mt = blockIdx.x >> 4;
    const int m0 = mt * CTA_M;
    const int n0 = nt * CTA_N;

    // Incremental global source pointers
    const __half* aptr = g_xh + (size_t)m0 * K_TOTAL;
    const __half* bptr = g_wh + n0;

    // Prologue: tile 0 -> stage 0 (issue before anything else)
    load_tile(abase, 0, aptr, bptr, tid);
    asm volatile("cp.async.commit_group;" ::: "memory");
    aptr += K_TILE;
    bptr += (size_t)K_TILE * N_TOTAL;

    float* psc = reinterpret_cast<float*>(smp + OFF_SC);
    float* pzz = reinterpret_cast<float*>(smp + OFF_ZZ);
    float* pbb = reinterpret_cast<float*>(smp + OFF_BB);
    if (tid < CTA_N) {
        psc[tid] = sc[n0 + tid];
        pzz[tid] = zz[n0 + tid];
        pbb[tid] = bb[n0 + tid];
    }

    // Per-thread ldmatrix address invariants
    const int la = lane & 15, lb = lane >> 4;
    const uint32_t axor = (uint32_t)((la & 7) << 4);
    uint32_t a_row[4];
#pragma unroll
    for (int m = 0; m < 4; m++)
        a_row[m] = (uint32_t)((warp_m * 64 + m * 16 + la) * 256);
    const uint32_t bxor = (uint32_t)((la & 7) << 4);
    const uint32_t b_la = (uint32_t)(la * 512);
    const uint32_t nb_base = (uint32_t)(warp_n * 128 + lb * 16);

    float acc[4][8][4];
#pragma unroll
    for (int m = 0; m < 4; m++)
#pragma unroll
        for (int nf = 0; nf < 8; nf++)
#pragma unroll
            for (int v = 0; v < 4; v++) acc[m][nf][v] = 0.f;

    uint32_t A[2][4][4];   // [buf][m frag][reg]
    uint32_t Bv[2][4][4];  // [buf][16n group][reg]

    // Wait for tile 0; preload ks=0 fragments
    asm volatile("cp.async.wait_group 0;" ::: "memory");
    __syncthreads();
    {
        const uint32_t a_s = abase + OFF_A;
        const uint32_t b_s = abase + OFF_B;
#pragma unroll
        for (int m = 0; m < 4; m++)
            ldsm4(A[0][m], a_s + a_row[m] + (((uint32_t)(lb * 16)) ^ axor));
#pragma unroll
        for (int nn = 0; nn < 4; nn++)
            ldsm4t(Bv[0][nn], b_s + b_la + ((nb_base + nn * 32) ^ bxor));
    }

#pragma unroll 2
    for (int kt = 0; kt < NK; kt++) {
        const int stage = kt & 1;
        const uint32_t a_s = abase + OFF_A + stage * A_BYTES;
        const uint32_t b_s = abase + OFF_B + stage * B_BYTES;

        // Issue loads for tile kt+1 into the other stage (its readers all
        // finished before the mid-iteration barrier of iteration kt-1).
        if (kt + 1 < NK) {
            load_tile(abase, stage ^ 1, aptr, bptr, tid);
            aptr += K_TILE;
            bptr += (size_t)K_TILE * N_TOTAL;
        }
        asm volatile("cp.async.commit_group;" ::: "memory");

#pragma unroll
        for (int ks = 0; ks < KCH - 1; ks++) {
            const int cur = ks & 1, nxt = cur ^ 1;
            // Prefetch fragments for ks+1 (same stage)
#pragma unroll
            for (int m = 0; m < 4; m++)
                ldsm4(A[nxt][m], a_s + a_row[m] +
                      (((uint32_t)((ks + 1) * 32 + lb * 16)) ^ axor));
            const uint32_t b_row = (uint32_t)((ks + 1) * 16 * 512) + b_la;
#pragma unroll
            for (int nn = 0; nn < 4; nn++)
                ldsm4t(Bv[nxt][nn], b_s + b_row + ((nb_base + nn * 32) ^ bxor));

#pragma unroll
            for (int m = 0; m < 4; m++)
#pragma unroll
                for (int nf = 0; nf < 8; nf++)
                    mma16816(acc[m][nf], A[cur][m], Bv[cur][nf >> 1][(nf & 1) * 2],
                             Bv[cur][nf >> 1][(nf & 1) * 2 + 1]);

            if (ks == WAIT_KS) {
                // Tile kt+1 arrival; DRAM idle -> loads land early, so take the
                // barrier early and leave 4 chunks of work to absorb warp skew.
                asm volatile("cp.async.wait_group 0;" ::: "memory");
                __syncthreads();
            }
        }

        // Cross-tile prefetch: ks=0 fragments of tile kt+1 from the other stage
        const int lastbuf = (KCH - 1) & 1;
        if (kt + 1 < NK) {
            const uint32_t a_n = abase + OFF_A + (stage ^ 1) * A_BYTES;
            const uint32_t b_n = abase + OFF_B + (stage ^ 1) * B_BYTES;
#pragma unroll
            for (int m = 0; m < 4; m++)
                ldsm4(A[lastbuf ^ 1][m], a_n + a_row[m] + (((uint32_t)(lb * 16)) ^ axor));
#pragma unroll
            for (int nn = 0; nn < 4; nn++)
                ldsm4t(Bv[lastbuf ^ 1][nn], b_n + b_la + ((nb_base + nn * 32) ^ bxor));
        }

        // Last mma chunk of tile kt (fragments in buf `lastbuf`)
#pragma unroll
        for (int m = 0; m < 4; m++)
#pragma unroll
            for (int nf = 0; nf < 8; nf++)
                mma16816(acc[m][nf], A[lastbuf][m], Bv[lastbuf][nf >> 1][(nf & 1) * 2],
                         Bv[lastbuf][nf >> 1][(nf & 1) * 2 + 1]);
        // Next iteration expects ks0 fragments in buf 0; KCH=8 -> lastbuf=1 ✓
    }

    // Epilogue: out = sc*acc - zz*rowsum + bias (streaming stores)
    const int r = lane >> 2;
    const int q2 = (lane & 3) * 2;
#pragma unroll
    for (int m = 0; m < 4; m++) {
        const int row = m0 + warp_m * 64 + m * 16 + r;
        const float rs0 = g_rowsum[row];
        const float rs1 = g_rowsum[row + 8];
        float* o0 = out + (size_t)row * N_TOTAL + n0;
        float* o1 = o0 + (size_t)8 * N_TOTAL;
#pragma unroll
        for (int nf = 0; nf < 8; nf++) {
            const int nl = warp_n * 64 + nf * 8 + q2;
            const float s0 = psc[nl], s1 = psc[nl + 1];
            const float z0 = pzz[nl], z1 = pzz[nl + 1];
            const float c0 = pbb[nl], c1 = pbb[nl + 1];
            float2 v0, v1;
            v0.x = fmaf(s0, acc[m][nf][0], fmaf(-z0, rs0, c0));
            v0.y = fmaf(s1, acc[m][nf][1], fmaf(-z1, rs0, c1));
            v1.x = fmaf(s0, acc[m][nf][2], fmaf(-z0, rs1, c0));
            v1.y = fmaf(s1, acc[m][nf][3], fmaf(-z1, rs1, c1));
            stcs2(o0 + nl, v0);
            stcs2(o1 + nl, v1);
        }
    }
}

// ----------------------------------------------------------------------------
// Launch
// ----------------------------------------------------------------------------
extern "C" void kernel_launch(void* const* d_in, const int* in_sizes, int n_in,
                              void* d_out, int out_size) {
    const float* x  = (const float*)d_in[0];
    const int*   qw = (const int*)d_in[1];
    const float* sc = (const float*)d_in[2];
    const float* zz = (const float*)d_in[3];
    const float* bb = (const float*)d_in[4];
    float* out = (float*)d_out;

    const int dq_blocks = (K_TOTAL / 8) * (N_TOTAL / 8) / 256;   // 1024
    prepass_kernel<<<M_TOTAL + dq_blocks, 256>>>(x, qw);

    cudaFuncSetAttribute(gemm_kernel, cudaFuncAttributeMaxDynamicSharedMemorySize, SMEM_BYTES);
    const int grid = (M_TOTAL / CTA_M) * (N_TOTAL / CTA_N);   // 64*16 = 1024
    gemm_kernel<<<grid, NTH, SMEM_BYTES>>>(sc, zz, bb, out);
}

// round 11
// speedup vs baseline: 1.8077x; 1.8077x over previous
#include <cuda_runtime.h>
#include <cuda_fp16.h>
#include <cstdint>

// ----------------------------------------------------------------------------
// Problem constants
// ----------------------------------------------------------------------------
#define M_TOTAL 8192   // B*S
#define K_TOTAL 4096   // IN
#define N_TOTAL 4096   // OUT

#define CTA_M 128
#define CTA_N 256
#define K_TILE 128
#define NK     (K_TOTAL / K_TILE)   // 32
#define STAGES 2
#define NTH    256

// Static device scratch (allowed; no dynamic allocation anywhere)
__device__ __align__(128) __half g_xh[(size_t)M_TOTAL * K_TOTAL];   // fp16 x, 64MB
__device__ __align__(128) __half g_wh[(size_t)K_TOTAL * N_TOTAL];   // fp16 q (0..15 exact), 32MB
__device__ float g_rowsum[M_TOTAL];                                  // exact fp32 row sums

// ----------------------------------------------------------------------------
// Helpers (arch-agnostic ISA only: cp.async, ldmatrix, mma.sync)
// ----------------------------------------------------------------------------
__device__ __forceinline__ uint32_t smem_u32(const void* p) {
    uint32_t a;
    asm("{ .reg .u64 t; cvta.to.shared.u64 t, %1; cvt.u32.u64 %0, t; }"
        : "=r"(a) : "l"(p));
    return a;
}

__device__ __forceinline__ void cp16(uint32_t dst, const void* src) {
    asm volatile("cp.async.cg.shared.global [%0], [%1], 16;" :: "r"(dst), "l"(src));
}

__device__ __forceinline__ void ldsm4(uint32_t* r, uint32_t a) {
    asm volatile("ldmatrix.sync.aligned.m8n8.x4.shared.b16 {%0,%1,%2,%3}, [%4];"
        : "=r"(r[0]), "=r"(r[1]), "=r"(r[2]), "=r"(r[3]) : "r"(a));
}

__device__ __forceinline__ void ldsm4t(uint32_t* r, uint32_t a) {
    asm volatile("ldmatrix.sync.aligned.m8n8.x4.trans.shared.b16 {%0,%1,%2,%3}, [%4];"
        : "=r"(r[0]), "=r"(r[1]), "=r"(r[2]), "=r"(r[3]) : "r"(a));
}

__device__ __forceinline__ void mma16816(float* c, const uint32_t* a,
                                         uint32_t b0, uint32_t b1) {
    asm volatile("mma.sync.aligned.m16n8k16.row.col.f32.f16.f16.f32 "
        "{%0,%1,%2,%3}, {%4,%5,%6,%7}, {%8,%9}, {%0,%1,%2,%3};"
        : "+f"(c[0]), "+f"(c[1]), "+f"(c[2]), "+f"(c[3])
        : "r"(a[0]), "r"(a[1]), "r"(a[2]), "r"(a[3]), "r"(b0), "r"(b1));
}

__device__ __forceinline__ void stcs2(float* p, float2 v) {
    asm volatile("st.global.cs.v2.f32 [%0], {%1, %2};" :: "l"(p), "f"(v.x), "f"(v.y) : "memory");
}

// ----------------------------------------------------------------------------
// Merged prepass:
//   blocks [0, M_TOTAL)          : x fp32 -> fp16 + exact fp32 row sums
//   blocks [M_TOTAL, M_TOTAL+1024): unpack int4 -> fp16 (0..15 exact), 16B stores
// ----------------------------------------------------------------------------
__global__ void __launch_bounds__(256) prepass_kernel(const float* __restrict__ x,
                                                      const int* __restrict__ qw) {
    if (blockIdx.x < M_TOTAL) {
        const int m = blockIdx.x;
        const float4* xr = reinterpret_cast<const float4*>(x + (size_t)m * K_TOTAL);
        __half2* xo = reinterpret_cast<__half2*>(g_xh + (size_t)m * K_TOTAL);
        float s = 0.f;
#pragma unroll
        for (int i = threadIdx.x; i < K_TOTAL / 4; i += 256) {
            float4 v = xr[i];
            s += (v.x + v.y) + (v.z + v.w);
            xo[2 * i]     = __floats2half2_rn(v.x, v.y);
            xo[2 * i + 1] = __floats2half2_rn(v.z, v.w);
        }
#pragma unroll
        for (int o = 16; o; o >>= 1) s += __shfl_xor_sync(0xFFFFFFFFu, s, o);
        __shared__ float ws[8];
        if ((threadIdx.x & 31) == 0) ws[threadIdx.x >> 5] = s;
        __syncthreads();
        if (threadIdx.x == 0) {
            float t = 0.f;
#pragma unroll
            for (int i = 0; i < 8; i++) t += ws[i];
            g_rowsum[m] = t;
        }
    } else {
        const int idx = (blockIdx.x - M_TOTAL) * 256 + threadIdx.x; // 0..(K/8)*(N/8)-1
        const int p  = idx >> 9;                          // packed row (N/8 = 512 groups)
        const int n8 = (idx & 511) * 8;
        const uint4* q = reinterpret_cast<const uint4*>(qw + (size_t)p * N_TOTAL + n8);
        uint4 w0 = q[0], w1 = q[1];
        uint32_t w[8] = {w0.x, w0.y, w0.z, w0.w, w1.x, w1.y, w1.z, w1.w};
        const uint32_t MAGIC = 0x64006400u;               // fp16x2 (1024,1024)
        const __half2 mh = *reinterpret_cast<const __half2*>(&MAGIC);
#pragma unroll
        for (int j = 0; j < 8; j++) {
            uint32_t o[4];
#pragma unroll
            for (int t = 0; t < 4; t++) {
                uint32_t lo = (w[2 * t]     >> (4 * j)) & 0xFu;
                uint32_t hi = (w[2 * t + 1] >> (4 * j)) & 0xFu;
                uint32_t u = lo | (hi << 16) | MAGIC;
                __half2 h = __hsub2(*reinterpret_cast<const __half2*>(&u), mh);
                o[t] = *reinterpret_cast<uint32_t*>(&h);
            }
            *reinterpret_cast<uint4*>(g_wh + (size_t)(p * 8 + j) * N_TOTAL + n8) =
                make_uint4(o[0], o[1], o[2], o[3]);
        }
    }
}

// ----------------------------------------------------------------------------
// GEMM: D[m][n] = sum_k xh[m][k] * wh[k][n]   (fp16 inputs, fp32 accum)
// CTA 128x256, warp grid 2(M) x 4(N), warp tile 64x64, K_TILE=128, 2 stages.
// Mid-iteration wait at ks=KCH-2 (correctness-pinned for the 2-stage ring:
// after this barrier no warp reads the current stage again, so the next
// iteration may overwrite it) + cross-tile fragment prefetch.
// Epilogue: out = sc*D - zz*rowsum + bias
// ----------------------------------------------------------------------------
// SMEM layout (relative to 1024-aligned base)
#define OFF_SC 0
#define OFF_ZZ 1024
#define OFF_BB 2048
#define OFF_A  3072                 // 2 x 32KB: [128 rows m][128 halves k], 256B rows
#define A_BYTES 32768
#define OFF_B  (OFF_A + STAGES * A_BYTES)   // 2 x 64KB: [128 rows k][256 halves n], 512B rows
#define B_BYTES 65536
#define SMEM_USED (OFF_B + STAGES * B_BYTES)
#define SMEM_BYTES (SMEM_USED + 1024)

#define KCH (K_TILE / 16)    // 8 k-chunks per tile

__device__ __forceinline__ void load_tile(uint32_t abase, int stage,
                                          const __half* __restrict__ asrc,
                                          const __half* __restrict__ bsrc,
                                          int tid) {
    // A tile: rows m (128), cols k (128 halves = 256B). swz within 128B half.
    const uint32_t a_s = abase + OFF_A + stage * A_BYTES;
#pragma unroll
    for (int it = 0; it < 2048 / NTH; it++) {
        int i = tid + it * NTH;
        int r = i >> 4, c = i & 15;
        uint32_t off = (uint32_t)(r * 256 + ((c * 16) ^ ((r & 7) << 4)));
        cp16(a_s + off, asrc + (size_t)r * K_TOTAL + c * 8);
    }
    // B tile: rows k (128), cols n (256 halves = 512B). swz within 128B region.
    const uint32_t b_s = abase + OFF_B + stage * B_BYTES;
#pragma unroll
    for (int it = 0; it < 4096 / NTH; it++) {
        int i = tid + it * NTH;
        int r = i >> 5, c = i & 31;
        uint32_t off = (uint32_t)(r * 512 + ((c * 16) ^ ((r & 7) << 4)));
        cp16(b_s + off, bsrc + (size_t)r * N_TOTAL + c * 8);
    }
}

__global__ void __launch_bounds__(NTH, 1)
gemm_kernel(const float* __restrict__ sc, const float* __restrict__ zz,
            const float* __restrict__ bb, float* __restrict__ out) {
    extern __shared__ char dsm[];
    const uint32_t raw = smem_u32(dsm);
    const uint32_t abase = (raw + 1023u) & ~1023u;
    char* smp = dsm + (abase - raw);

    const int tid = threadIdx.x;
    const int lane = tid & 31;
    const int wid = tid >> 5;
    const int warp_m = wid & 1;        // 2 warps over M (64 rows each)
    const int warp_n = wid >> 1;       // 4 warps over N (64 cols each)
    const int nt = blockIdx.x & 15;    // N fastest -> B stays L2-resident
    const int mt = blockIdx.x >> 4;
    const int m0 = mt * CTA_M;
    const int n0 = nt * CTA_N;

    // Incremental global source pointers
    const __half* aptr = g_xh + (size_t)m0 * K_TOTAL;
    const __half* bptr = g_wh + n0;

    // Prologue: tile 0 -> stage 0 (issue before anything else)
    load_tile(abase, 0, aptr, bptr, tid);
    asm volatile("cp.async.commit_group;" ::: "memory");
    aptr += K_TILE;
    bptr += (size_t)K_TILE * N_TOTAL;

    float* psc = reinterpret_cast<float*>(smp + OFF_SC);
    float* pzz = reinterpret_cast<float*>(smp + OFF_ZZ);
    float* pbb = reinterpret_cast<float*>(smp + OFF_BB);
    if (tid < CTA_N) {
        psc[tid] = sc[n0 + tid];
        pzz[tid] = zz[n0 + tid];
        pbb[tid] = bb[n0 + tid];
    }

    // Per-thread ldmatrix address invariants
    const int la = lane & 15, lb = lane >> 4;
    const uint32_t axor = (uint32_t)((la & 7) << 4);
    uint32_t a_row[4];
#pragma unroll
    for (int m = 0; m < 4; m++)
        a_row[m] = (uint32_t)((warp_m * 64 + m * 16 + la) * 256);
    const uint32_t bxor = (uint32_t)((la & 7) << 4);
    const uint32_t b_la = (uint32_t)(la * 512);
    const uint32_t nb_base = (uint32_t)(warp_n * 128 + lb * 16);

    float acc[4][8][4];
#pragma unroll
    for (int m = 0; m < 4; m++)
#pragma unroll
        for (int nf = 0; nf < 8; nf++)
#pragma unroll
            for (int v = 0; v < 4; v++) acc[m][nf][v] = 0.f;

    uint32_t A[2][4][4];   // [buf][m frag][reg]
    uint32_t Bv[2][4][4];  // [buf][16n group][reg]

    // Wait for tile 0; preload ks=0 fragments
    asm volatile("cp.async.wait_group 0;" ::: "memory");
    __syncthreads();
    {
        const uint32_t a_s = abase + OFF_A;
        const uint32_t b_s = abase + OFF_B;
#pragma unroll
        for (int m = 0; m < 4; m++)
            ldsm4(A[0][m], a_s + a_row[m] + (((uint32_t)(lb * 16)) ^ axor));
#pragma unroll
        for (int nn = 0; nn < 4; nn++)
            ldsm4t(Bv[0][nn], b_s + b_la + ((nb_base + nn * 32) ^ bxor));
    }

    for (int kt = 0; kt < NK; kt++) {
        const int stage = kt & 1;
        const uint32_t a_s = abase + OFF_A + stage * A_BYTES;
        const uint32_t b_s = abase + OFF_B + stage * B_BYTES;

        // Issue loads for tile kt+1 into the other stage (its readers all
        // finished before the ks=KCH-2 barrier of iteration kt-1).
        if (kt + 1 < NK) {
            load_tile(abase, stage ^ 1, aptr, bptr, tid);
            aptr += K_TILE;
            bptr += (size_t)K_TILE * N_TOTAL;
        }
        asm volatile("cp.async.commit_group;" ::: "memory");

#pragma unroll
        for (int ks = 0; ks < KCH - 1; ks++) {
            const int cur = ks & 1, nxt = cur ^ 1;
            // Prefetch fragments for ks+1 (same stage)
#pragma unroll
            for (int m = 0; m < 4; m++)
                ldsm4(A[nxt][m], a_s + a_row[m] +
                      (((uint32_t)((ks + 1) * 32 + lb * 16)) ^ axor));
            const uint32_t b_row = (uint32_t)((ks + 1) * 16 * 512) + b_la;
#pragma unroll
            for (int nn = 0; nn < 4; nn++)
                ldsm4t(Bv[nxt][nn], b_s + b_row + ((nb_base + nn * 32) ^ bxor));

#pragma unroll
            for (int m = 0; m < 4; m++)
#pragma unroll
                for (int nf = 0; nf < 8; nf++)
                    mma16816(acc[m][nf], A[cur][m], Bv[cur][nf >> 1][(nf & 1) * 2],
                             Bv[cur][nf >> 1][(nf & 1) * 2 + 1]);

            if (ks == KCH - 2) {
                // Tile kt+1 arrival. CORRECTNESS-PINNED position: after this
                // barrier no warp reads the current stage again, so iteration
                // kt+1 may safely overwrite it. Do NOT move earlier (R9 race).
                asm volatile("cp.async.wait_group 0;" ::: "memory");
                __syncthreads();
            }
        }

        // Cross-tile prefetch: ks=0 fragments of tile kt+1 from the other stage
        const int lastbuf = (KCH - 1) & 1;
        if (kt + 1 < NK) {
            const uint32_t a_n = abase + OFF_A + (stage ^ 1) * A_BYTES;
            const uint32_t b_n = abase + OFF_B + (stage ^ 1) * B_BYTES;
#pragma unroll
            for (int m = 0; m < 4; m++)
                ldsm4(A[lastbuf ^ 1][m], a_n + a_row[m] + (((uint32_t)(lb * 16)) ^ axor));
#pragma unroll
            for (int nn = 0; nn < 4; nn++)
                ldsm4t(Bv[lastbuf ^ 1][nn], b_n + b_la + ((nb_base + nn * 32) ^ bxor));
        }

        // Last mma chunk of tile kt (fragments in buf `lastbuf`)
#pragma unroll
        for (int m = 0; m < 4; m++)
#pragma unroll
            for (int nf = 0; nf < 8; nf++)
                mma16816(acc[m][nf], A[lastbuf][m], Bv[lastbuf][nf >> 1][(nf & 1) * 2],
                         Bv[lastbuf][nf >> 1][(nf & 1) * 2 + 1]);
        // Next iteration expects ks0 fragments in buf 0; KCH=8 -> lastbuf=1 ✓
    }

    // Epilogue: out = sc*acc - zz*rowsum + bias (streaming stores)
    const int r = lane >> 2;
    const int q2 = (lane & 3) * 2;
#pragma unroll
    for (int m = 0; m < 4; m++) {
        const int row = m0 + warp_m * 64 + m * 16 + r;
        const float rs0 = g_rowsum[row];
        const float rs1 = g_rowsum[row + 8];
        float* o0 = out + (size_t)row * N_TOTAL + n0;
        float* o1 = o0 + (size_t)8 * N_TOTAL;
#pragma unroll
        for (int nf = 0; nf < 8; nf++) {
            const int nl = warp_n * 64 + nf * 8 + q2;
            const float s0 = psc[nl], s1 = psc[nl + 1];
            const float z0 = pzz[nl], z1 = pzz[nl + 1];
            const float c0 = pbb[nl], c1 = pbb[nl + 1];
            float2 v0, v1;
            v0.x = fmaf(s0, acc[m][nf][0], fmaf(-z0, rs0, c0));
            v0.y = fmaf(s1, acc[m][nf][1], fmaf(-z1, rs0, c1));
            v1.x = fmaf(s0, acc[m][nf][2], fmaf(-z0, rs1, c0));
            v1.y = fmaf(s1, acc[m][nf][3], fmaf(-z1, rs1, c1));
            stcs2(o0 + nl, v0);
            stcs2(o1 + nl, v1);
        }
    }
}

// ----------------------------------------------------------------------------
// Launch
// ----------------------------------------------------------------------------
extern "C" void kernel_launch(void* const* d_in, const int* in_sizes, int n_in,
                              void* d_out, int out_size) {
    const float* x  = (const float*)d_in[0];
    const int*   qw = (const int*)d_in[1];
    const float* sc = (const float*)d_in[2];
    const float* zz = (const float*)d_in[3];
    const float* bb = (const float*)d_in[4];
    float* out = (float*)d_out;

    const int dq_blocks = (K_TOTAL / 8) * (N_TOTAL / 8) / 256;   // 1024
    prepass_kernel<<<M_TOTAL + dq_blocks, 256>>>(x, qw);

    cudaFuncSetAttribute(gemm_kernel, cudaFuncAttributeMaxDynamicSharedMemorySize, SMEM_BYTES);
    const int grid = (M_TOTAL / CTA_M) * (N_TOTAL / CTA_N);   // 64*16 = 1024
    gemm_kernel<<<grid, NTH, SMEM_BYTES>>>(sc, zz, bb, out);
}

// round 12
// speedup vs baseline: 1.8103x; 1.0014x over previous
#include <cuda_runtime.h>
#include <cuda_fp16.h>
#include <cstdint>

// ----------------------------------------------------------------------------
// Problem constants
// ----------------------------------------------------------------------------
#define M_TOTAL 8192   // B*S
#define K_TOTAL 4096   // IN
#define N_TOTAL 4096   // OUT

#define CTA_M 128
#define CTA_N 256
#define K_TILE 128
#define NK     (K_TOTAL / K_TILE)   // 32
#define STAGES 2
#define NTH    256

// Static device scratch (allowed; no dynamic allocation anywhere)
__device__ __align__(128) __half g_xh[(size_t)M_TOTAL * K_TOTAL];   // fp16 x, 64MB
__device__ __align__(128) __half g_wh[(size_t)K_TOTAL * N_TOTAL];   // fp16 q (0..15 exact), 32MB
__device__ float g_rowsum[M_TOTAL];                                  // exact fp32 row sums

// ----------------------------------------------------------------------------
// Helpers (arch-agnostic ISA only: cp.async, ldmatrix, mma.sync)
// ----------------------------------------------------------------------------
__device__ __forceinline__ uint32_t smem_u32(const void* p) {
    uint32_t a;
    asm("{ .reg .u64 t; cvta.to.shared.u64 t, %1; cvt.u32.u64 %0, t; }"
        : "=r"(a) : "l"(p));
    return a;
}

__device__ __forceinline__ void cp16(uint32_t dst, const void* src) {
    asm volatile("cp.async.cg.shared.global [%0], [%1], 16;" :: "r"(dst), "l"(src));
}

__device__ __forceinline__ void ldsm4(uint32_t* r, uint32_t a) {
    asm volatile("ldmatrix.sync.aligned.m8n8.x4.shared.b16 {%0,%1,%2,%3}, [%4];"
        : "=r"(r[0]), "=r"(r[1]), "=r"(r[2]), "=r"(r[3]) : "r"(a));
}

__device__ __forceinline__ void ldsm4t(uint32_t* r, uint32_t a) {
    asm volatile("ldmatrix.sync.aligned.m8n8.x4.trans.shared.b16 {%0,%1,%2,%3}, [%4];"
        : "=r"(r[0]), "=r"(r[1]), "=r"(r[2]), "=r"(r[3]) : "r"(a));
}

__device__ __forceinline__ void mma16816(float* c, const uint32_t* a,
                                         uint32_t b0, uint32_t b1) {
    asm volatile("mma.sync.aligned.m16n8k16.row.col.f32.f16.f16.f32 "
        "{%0,%1,%2,%3}, {%4,%5,%6,%7}, {%8,%9}, {%0,%1,%2,%3};"
        : "+f"(c[0]), "+f"(c[1]), "+f"(c[2]), "+f"(c[3])
        : "r"(a[0]), "r"(a[1]), "r"(a[2]), "r"(a[3]), "r"(b0), "r"(b1));
}

__device__ __forceinline__ void stcs2(float* p, float2 v) {
    asm volatile("st.global.cs.v2.f32 [%0], {%1, %2};" :: "l"(p), "f"(v.x), "f"(v.y) : "memory");
}

// ----------------------------------------------------------------------------
// Merged prepass:
//   blocks [0, M_TOTAL)          : x fp32 -> fp16 + exact fp32 row sums
//   blocks [M_TOTAL, M_TOTAL+1024): unpack int4 -> fp16 (0..15 exact), 16B stores
// ----------------------------------------------------------------------------
__global__ void __launch_bounds__(256) prepass_kernel(const float* __restrict__ x,
                                                      const int* __restrict__ qw) {
    if (blockIdx.x < M_TOTAL) {
        const int m = blockIdx.x;
        const float4* xr = reinterpret_cast<const float4*>(x + (size_t)m * K_TOTAL);
        __half2* xo = reinterpret_cast<__half2*>(g_xh + (size_t)m * K_TOTAL);
        float s = 0.f;
#pragma unroll
        for (int i = threadIdx.x; i < K_TOTAL / 4; i += 256) {
            float4 v = xr[i];
            s += (v.x + v.y) + (v.z + v.w);
            xo[2 * i]     = __floats2half2_rn(v.x, v.y);
            xo[2 * i + 1] = __floats2half2_rn(v.z, v.w);
        }
#pragma unroll
        for (int o = 16; o; o >>= 1) s += __shfl_xor_sync(0xFFFFFFFFu, s, o);
        __shared__ float ws[8];
        if ((threadIdx.x & 31) == 0) ws[threadIdx.x >> 5] = s;
        __syncthreads();
        if (threadIdx.x == 0) {
            float t = 0.f;
#pragma unroll
            for (int i = 0; i < 8; i++) t += ws[i];
            g_rowsum[m] = t;
        }
    } else {
        const int idx = (blockIdx.x - M_TOTAL) * 256 + threadIdx.x; // 0..(K/8)*(N/8)-1
        const int p  = idx >> 9;                          // packed row (N/8 = 512 groups)
        const int n8 = (idx & 511) * 8;
        const uint4* q = reinterpret_cast<const uint4*>(qw + (size_t)p * N_TOTAL + n8);
        uint4 w0 = q[0], w1 = q[1];
        uint32_t w[8] = {w0.x, w0.y, w0.z, w0.w, w1.x, w1.y, w1.z, w1.w};
        const uint32_t MAGIC = 0x64006400u;               // fp16x2 (1024,1024)
        const __half2 mh = *reinterpret_cast<const __half2*>(&MAGIC);
#pragma unroll
        for (int j = 0; j < 8; j++) {
            uint32_t o[4];
#pragma unroll
            for (int t = 0; t < 4; t++) {
                uint32_t lo = (w[2 * t]     >> (4 * j)) & 0xFu;
                uint32_t hi = (w[2 * t + 1] >> (4 * j)) & 0xFu;
                uint32_t u = lo | (hi << 16) | MAGIC;
                __half2 h = __hsub2(*reinterpret_cast<const __half2*>(&u), mh);
                o[t] = *reinterpret_cast<uint32_t*>(&h);
            }
            *reinterpret_cast<uint4*>(g_wh + (size_t)(p * 8 + j) * N_TOTAL + n8) =
                make_uint4(o[0], o[1], o[2], o[3]);
        }
    }
}

// ----------------------------------------------------------------------------
// GEMM: D[m][n] = sum_k xh[m][k] * wh[k][n]   (fp16 inputs, fp32 accum)
// CTA 128x256, warp grid 2(M) x 4(N), warp tile 64x64, K_TILE=128, 2 stages.
// Mid-iteration wait at ks=KCH-2 (correctness-pinned for the 2-stage ring).
// Next-tile loads issued in TWO halves (top + after chunk 2) to smooth the
// LSU/L2 burst. Epilogue: out = sc*D - zz*rowsum + bias
// ----------------------------------------------------------------------------
// SMEM layout (relative to 1024-aligned base)
#define OFF_SC 0
#define OFF_ZZ 1024
#define OFF_BB 2048
#define OFF_A  3072                 // 2 x 32KB: [128 rows m][128 halves k], 256B rows
#define A_BYTES 32768
#define OFF_B  (OFF_A + STAGES * A_BYTES)   // 2 x 64KB: [128 rows k][256 halves n], 512B rows
#define B_BYTES 65536
#define SMEM_USED (OFF_B + STAGES * B_BYTES)
#define SMEM_BYTES (SMEM_USED + 1024)

#define KCH (K_TILE / 16)    // 8 k-chunks per tile

// Half 1: full A tile + B rows 0..63
__device__ __forceinline__ void load_tile_p1(uint32_t abase, int stage,
                                             const __half* __restrict__ asrc,
                                             const __half* __restrict__ bsrc,
                                             int tid) {
    const uint32_t a_s = abase + OFF_A + stage * A_BYTES;
#pragma unroll
    for (int it = 0; it < 2048 / NTH; it++) {
        int i = tid + it * NTH;
        int r = i >> 4, c = i & 15;
        uint32_t off = (uint32_t)(r * 256 + ((c * 16) ^ ((r & 7) << 4)));
        cp16(a_s + off, asrc + (size_t)r * K_TOTAL + c * 8);
    }
    const uint32_t b_s = abase + OFF_B + stage * B_BYTES;
#pragma unroll
    for (int it = 0; it < 2048 / NTH; it++) {
        int i = tid + it * NTH;
        int r = i >> 5, c = i & 31;     // rows 0..63
        uint32_t off = (uint32_t)(r * 512 + ((c * 16) ^ ((r & 7) << 4)));
        cp16(b_s + off, bsrc + (size_t)r * N_TOTAL + c * 8);
    }
}

// Half 2: B rows 64..127
__device__ __forceinline__ void load_tile_p2(uint32_t abase, int stage,
                                             const __half* __restrict__ bsrc,
                                             int tid) {
    const uint32_t b_s = abase + OFF_B + stage * B_BYTES;
#pragma unroll
    for (int it = 0; it < 2048 / NTH; it++) {
        int i = tid + it * NTH + 2048;
        int r = i >> 5, c = i & 31;     // rows 64..127
        uint32_t off = (uint32_t)(r * 512 + ((c * 16) ^ ((r & 7) << 4)));
        cp16(b_s + off, bsrc + (size_t)r * N_TOTAL + c * 8);
    }
}

__global__ void __launch_bounds__(NTH, 1)
gemm_kernel(const float* __restrict__ sc, const float* __restrict__ zz,
            const float* __restrict__ bb, float* __restrict__ out) {
    extern __shared__ char dsm[];
    const uint32_t raw = smem_u32(dsm);
    const uint32_t abase = (raw + 1023u) & ~1023u;
    char* smp = dsm + (abase - raw);

    const int tid = threadIdx.x;
    const int lane = tid & 31;
    const int wid = tid >> 5;
    const int warp_m = wid & 1;        // 2 warps over M (64 rows each)
    const int warp_n = wid >> 1;       // 4 warps over N (64 cols each)
    const int nt = blockIdx.x & 15;    // N fastest -> B stays L2-resident
    const int mt = blockIdx.x >> 4;
    const int m0 = mt * CTA_M;
    const int n0 = nt * CTA_N;

    // Incremental global source pointers
    const __half* aptr = g_xh + (size_t)m0 * K_TOTAL;
    const __half* bptr = g_wh + n0;

    // Prologue: tile 0 -> stage 0 (issue before anything else)
    load_tile_p1(abase, 0, aptr, bptr, tid);
    load_tile_p2(abase, 0, bptr, tid);
    asm volatile("cp.async.commit_group;" ::: "memory");
    aptr += K_TILE;
    bptr += (size_t)K_TILE * N_TOTAL;

    float* psc = reinterpret_cast<float*>(smp + OFF_SC);
    float* pzz = reinterpret_cast<float*>(smp + OFF_ZZ);
    float* pbb = reinterpret_cast<float*>(smp + OFF_BB);
    if (tid < CTA_N) {
        psc[tid] = sc[n0 + tid];
        pzz[tid] = zz[n0 + tid];
        pbb[tid] = bb[n0 + tid];
    }

    // Per-thread ldmatrix address invariants
    const int la = lane & 15, lb = lane >> 4;
    const uint32_t axor = (uint32_t)((la & 7) << 4);
    uint32_t a_row[4];
#pragma unroll
    for (int m = 0; m < 4; m++)
        a_row[m] = (uint32_t)((warp_m * 64 + m * 16 + la) * 256);
    const uint32_t bxor = (uint32_t)((la & 7) << 4);
    const uint32_t b_la = (uint32_t)(la * 512);
    const uint32_t nb_base = (uint32_t)(warp_n * 128 + lb * 16);

    float acc[4][8][4];
#pragma unroll
    for (int m = 0; m < 4; m++)
#pragma unroll
        for (int nf = 0; nf < 8; nf++)
#pragma unroll
            for (int v = 0; v < 4; v++) acc[m][nf][v] = 0.f;

    uint32_t A[2][4][4];   // [buf][m frag][reg]
    uint32_t Bv[2][4][4];  // [buf][16n group][reg]

    // Wait for tile 0; preload ks=0 fragments
    asm volatile("cp.async.wait_group 0;" ::: "memory");
    __syncthreads();
    {
        const uint32_t a_s = abase + OFF_A;
        const uint32_t b_s = abase + OFF_B;
#pragma unroll
        for (int m = 0; m < 4; m++)
            ldsm4(A[0][m], a_s + a_row[m] + (((uint32_t)(lb * 16)) ^ axor));
#pragma unroll
        for (int nn = 0; nn < 4; nn++)
            ldsm4t(Bv[0][nn], b_s + b_la + ((nb_base + nn * 32) ^ bxor));
    }

    for (int kt = 0; kt < NK; kt++) {
        const int stage = kt & 1;
        const uint32_t a_s = abase + OFF_A + stage * A_BYTES;
        const uint32_t b_s = abase + OFF_B + stage * B_BYTES;
        const bool more = (kt + 1 < NK);
        const __half* bcur = bptr;     // tile kt+1 B source (before increment)

        // Half 1 of tile kt+1 loads (A + B rows 0..63). Stage^1 is safe to
        // write: its readers finished before the ks=KCH-2 barrier of kt-1.
        if (more) {
            load_tile_p1(abase, stage ^ 1, aptr, bcur, tid);
            aptr += K_TILE;
        }
        asm volatile("cp.async.commit_group;" ::: "memory");

#pragma unroll
        for (int ks = 0; ks < KCH - 1; ks++) {
            const int cur = ks & 1, nxt = cur ^ 1;
            // Prefetch fragments for ks+1 (same stage)
#pragma unroll
            for (int m = 0; m < 4; m++)
                ldsm4(A[nxt][m], a_s + a_row[m] +
                      (((uint32_t)((ks + 1) * 32 + lb * 16)) ^ axor));
            const uint32_t b_row = (uint32_t)((ks + 1) * 16 * 512) + b_la;
#pragma unroll
            for (int nn = 0; nn < 4; nn++)
                ldsm4t(Bv[nxt][nn], b_s + b_row + ((nb_base + nn * 32) ^ bxor));

#pragma unroll
            for (int m = 0; m < 4; m++)
#pragma unroll
                for (int nf = 0; nf < 8; nf++)
                    mma16816(acc[m][nf], A[cur][m], Bv[cur][nf >> 1][(nf & 1) * 2],
                             Bv[cur][nf >> 1][(nf & 1) * 2 + 1]);

            if (ks == 2) {
                // Half 2 of tile kt+1 loads (B rows 64..127): spreads the
                // LSU/L2 burst; still ~4 chunks for the data to land.
                if (more) {
                    load_tile_p2(abase, stage ^ 1, bcur, tid);
                    bptr += (size_t)K_TILE * N_TOTAL;
                }
                asm volatile("cp.async.commit_group;" ::: "memory");
            }

            if (ks == KCH - 2) {
                // Tile kt+1 arrival. CORRECTNESS-PINNED position: after this
                // barrier no warp reads the current stage again, so iteration
                // kt+1 may safely overwrite it. Do NOT move earlier (R9 race).
                asm volatile("cp.async.wait_group 0;" ::: "memory");
                __syncthreads();
            }
        }

        // Cross-tile prefetch: ks=0 fragments of tile kt+1 from the other stage
        const int lastbuf = (KCH - 1) & 1;
        if (more) {
            const uint32_t a_n = abase + OFF_A + (stage ^ 1) * A_BYTES;
            const uint32_t b_n = abase + OFF_B + (stage ^ 1) * B_BYTES;
#pragma unroll
            for (int m = 0; m < 4; m++)
                ldsm4(A[lastbuf ^ 1][m], a_n + a_row[m] + (((uint32_t)(lb * 16)) ^ axor));
#pragma unroll
            for (int nn = 0; nn < 4; nn++)
                ldsm4t(Bv[lastbuf ^ 1][nn], b_n + b_la + ((nb_base + nn * 32) ^ bxor));
        }

        // Last mma chunk of tile kt (fragments in buf `lastbuf`)
#pragma unroll
        for (int m = 0; m < 4; m++)
#pragma unroll
            for (int nf = 0; nf < 8; nf++)
                mma16816(acc[m][nf], A[lastbuf][m], Bv[lastbuf][nf >> 1][(nf & 1) * 2],
                         Bv[lastbuf][nf >> 1][(nf & 1) * 2 + 1]);
        // Next iteration expects ks0 fragments in buf 0; KCH=8 -> lastbuf=1 ✓
    }

    // Epilogue: out = sc*acc - zz*rowsum + bias (streaming stores)
    const int r = lane >> 2;
    const int q2 = (lane & 3) * 2;
#pragma unroll
    for (int m = 0; m < 4; m++) {
        const int row = m0 + warp_m * 64 + m * 16 + r;
        const float rs0 = g_rowsum[row];
        const float rs1 = g_rowsum[row + 8];
        float* o0 = out + (size_t)row * N_TOTAL + n0;
        float* o1 = o0 + (size_t)8 * N_TOTAL;
#pragma unroll
        for (int nf = 0; nf < 8; nf++) {
            const int nl = warp_n * 64 + nf * 8 + q2;
            const float s0 = psc[nl], s1 = psc[nl + 1];
            const float z0 = pzz[nl], z1 = pzz[nl + 1];
            const float c0 = pbb[nl], c1 = pbb[nl + 1];
            float2 v0, v1;
            v0.x = fmaf(s0, acc[m][nf][0], fmaf(-z0, rs0, c0));
            v0.y = fmaf(s1, acc[m][nf][1], fmaf(-z1, rs0, c1));
            v1.x = fmaf(s0, acc[m][nf][2], fmaf(-z0, rs1, c0));
            v1.y = fmaf(s1, acc[m][nf][3], fmaf(-z1, rs1, c1));
            stcs2(o0 + nl, v0);
            stcs2(o1 + nl, v1);
        }
    }
}

// ----------------------------------------------------------------------------
// Launch
// ----------------------------------------------------------------------------
extern "C" void kernel_launch(void* const* d_in, const int* in_sizes, int n_in,
                              void* d_out, int out_size) {
    const float* x  = (const float*)d_in[0];
    const int*   qw = (const int*)d_in[1];
    const float* sc = (const float*)d_in[2];
    const float* zz = (const float*)d_in[3];
    const float* bb = (const float*)d_in[4];
    float* out = (float*)d_out;

    const int dq_blocks = (K_TOTAL / 8) * (N_TOTAL / 8) / 256;   // 1024
    prepass_kernel<<<M_TOTAL + dq_blocks, 256>>>(x, qw);

    cudaFuncSetAttribute(gemm_kernel, cudaFuncAttributeMaxDynamicSharedMemorySize, SMEM_BYTES);
    const int grid = (M_TOTAL / CTA_M) * (N_TOTAL / CTA_N);   // 64*16 = 1024
    gemm_kernel<<<grid, NTH, SMEM_BYTES>>>(sc, zz, bb, out);
}

// round 13
// speedup vs baseline: 1.8104x; 1.0001x over previous
#include <cuda_runtime.h>
#include <cuda_fp16.h>
#include <cstdint>

// ----------------------------------------------------------------------------
// Problem constants
// ----------------------------------------------------------------------------
#define M_TOTAL 8192   // B*S
#define K_TOTAL 4096   // IN
#define N_TOTAL 4096   // OUT

#define CTA_M 128
#define CTA_N 256
#define K_TILE 128
#define NK     (K_TOTAL / K_TILE)   // 32
#define STAGES 2
#define NTH    256

// Static device scratch (allowed; no dynamic allocation anywhere)
__device__ __align__(128) __half g_xh[(size_t)M_TOTAL * K_TOTAL];   // fp16 x, 64MB
__device__ __align__(128) __half g_wh[(size_t)K_TOTAL * N_TOTAL];   // fp16 q (0..15 exact), 32MB
__device__ float g_rowsum[M_TOTAL];                                  // exact fp32 row sums

// ----------------------------------------------------------------------------
// Helpers (arch-agnostic ISA only: cp.async, ldmatrix, mma.sync)
// ----------------------------------------------------------------------------
__device__ __forceinline__ uint32_t smem_u32(const void* p) {
    uint32_t a;
    asm("{ .reg .u64 t; cvta.to.shared.u64 t, %1; cvt.u32.u64 %0, t; }"
        : "=r"(a) : "l"(p));
    return a;
}

__device__ __forceinline__ void cp16(uint32_t dst, const void* src) {
    asm volatile("cp.async.cg.shared.global [%0], [%1], 16;" :: "r"(dst), "l"(src));
}

__device__ __forceinline__ void ldsm4(uint32_t* r, uint32_t a) {
    asm volatile("ldmatrix.sync.aligned.m8n8.x4.shared.b16 {%0,%1,%2,%3}, [%4];"
        : "=r"(r[0]), "=r"(r[1]), "=r"(r[2]), "=r"(r[3]) : "r"(a));
}

__device__ __forceinline__ void ldsm4t(uint32_t* r, uint32_t a) {
    asm volatile("ldmatrix.sync.aligned.m8n8.x4.trans.shared.b16 {%0,%1,%2,%3}, [%4];"
        : "=r"(r[0]), "=r"(r[1]), "=r"(r[2]), "=r"(r[3]) : "r"(a));
}

__device__ __forceinline__ void mma16816(float* c, const uint32_t* a,
                                         uint32_t b0, uint32_t b1) {
    asm volatile("mma.sync.aligned.m16n8k16.row.col.f32.f16.f16.f32 "
        "{%0,%1,%2,%3}, {%4,%5,%6,%7}, {%8,%9}, {%0,%1,%2,%3};"
        : "+f"(c[0]), "+f"(c[1]), "+f"(c[2]), "+f"(c[3])
        : "r"(a[0]), "r"(a[1]), "r"(a[2]), "r"(a[3]), "r"(b0), "r"(b1));
}

__device__ __forceinline__ void stcs2(float* p, float2 v) {
    asm volatile("st.global.cs.v2.f32 [%0], {%1, %2};" :: "l"(p), "f"(v.x), "f"(v.y) : "memory");
}

// ----------------------------------------------------------------------------
// Merged prepass:
//   blocks [0, M_TOTAL)          : x fp32 -> fp16 + exact fp32 row sums
//   blocks [M_TOTAL, M_TOTAL+1024): unpack int4 -> fp16 (0..15 exact), 16B stores
// ----------------------------------------------------------------------------
__global__ void __launch_bounds__(256) prepass_kernel(const float* __restrict__ x,
                                                      const int* __restrict__ qw) {
    if (blockIdx.x < M_TOTAL) {
        const int m = blockIdx.x;
        const float4* xr = reinterpret_cast<const float4*>(x + (size_t)m * K_TOTAL);
        __half2* xo = reinterpret_cast<__half2*>(g_xh + (size_t)m * K_TOTAL);
        float s = 0.f;
#pragma unroll
        for (int i = threadIdx.x; i < K_TOTAL / 4; i += 256) {
            float4 v = xr[i];
            s += (v.x + v.y) + (v.z + v.w);
            xo[2 * i]     = __floats2half2_rn(v.x, v.y);
            xo[2 * i + 1] = __floats2half2_rn(v.z, v.w);
        }
#pragma unroll
        for (int o = 16; o; o >>= 1) s += __shfl_xor_sync(0xFFFFFFFFu, s, o);
        __shared__ float ws[8];
        if ((threadIdx.x & 31) == 0) ws[threadIdx.x >> 5] = s;
        __syncthreads();
        if (threadIdx.x == 0) {
            float t = 0.f;
#pragma unroll
            for (int i = 0; i < 8; i++) t += ws[i];
            g_rowsum[m] = t;
        }
    } else {
        const int idx = (blockIdx.x - M_TOTAL) * 256 + threadIdx.x; // 0..(K/8)*(N/8)-1
        const int p  = idx >> 9;                          // packed row (N/8 = 512 groups)
        const int n8 = (idx & 511) * 8;
        const uint4* q = reinterpret_cast<const uint4*>(qw + (size_t)p * N_TOTAL + n8);
        uint4 w0 = q[0], w1 = q[1];
        uint32_t w[8] = {w0.x, w0.y, w0.z, w0.w, w1.x, w1.y, w1.z, w1.w};
        const uint32_t MAGIC = 0x64006400u;               // fp16x2 (1024,1024)
        const __half2 mh = *reinterpret_cast<const __half2*>(&MAGIC);
#pragma unroll
        for (int j = 0; j < 8; j++) {
            uint32_t o[4];
#pragma unroll
            for (int t = 0; t < 4; t++) {
                uint32_t lo = (w[2 * t]     >> (4 * j)) & 0xFu;
                uint32_t hi = (w[2 * t + 1] >> (4 * j)) & 0xFu;
                uint32_t u = lo | (hi << 16) | MAGIC;
                __half2 h = __hsub2(*reinterpret_cast<const __half2*>(&u), mh);
                o[t] = *reinterpret_cast<uint32_t*>(&h);
            }
            *reinterpret_cast<uint4*>(g_wh + (size_t)(p * 8 + j) * N_TOTAL + n8) =
                make_uint4(o[0], o[1], o[2], o[3]);
        }
    }
}

// ----------------------------------------------------------------------------
// GEMM: D[m][n] = sum_k xh[m][k] * wh[k][n]   (fp16 inputs, fp32 accum)
// CTA 128x256, warp grid 2(M) x 4(N), warp tile 64x64, K_TILE=128, 2 stages.
// Mid-iteration wait at ks=KCH-2 (correctness-pinned for the 2-stage ring).
// Next-tile loads issued in TWO halves (top + after chunk 2) to smooth the
// LSU/L2 burst. Epilogue: out = sc*D - zz*rowsum + bias
// ----------------------------------------------------------------------------
// SMEM layout (relative to 1024-aligned base)
#define OFF_SC 0
#define OFF_ZZ 1024
#define OFF_BB 2048
#define OFF_A  3072                 // 2 x 32KB: [128 rows m][128 halves k], 256B rows
#define A_BYTES 32768
#define OFF_B  (OFF_A + STAGES * A_BYTES)   // 2 x 64KB: [128 rows k][256 halves n], 512B rows
#define B_BYTES 65536
#define SMEM_USED (OFF_B + STAGES * B_BYTES)
#define SMEM_BYTES (SMEM_USED + 1024)

#define KCH (K_TILE / 16)    // 8 k-chunks per tile

// Half 1: full A tile + B rows 0..63
__device__ __forceinline__ void load_tile_p1(uint32_t abase, int stage,
                                             const __half* __restrict__ asrc,
                                             const __half* __restrict__ bsrc,
                                             int tid) {
    const uint32_t a_s = abase + OFF_A + stage * A_BYTES;
#pragma unroll
    for (int it = 0; it < 2048 / NTH; it++) {
        int i = tid + it * NTH;
        int r = i >> 4, c = i & 15;
        uint32_t off = (uint32_t)(r * 256 + ((c * 16) ^ ((r & 7) << 4)));
        cp16(a_s + off, asrc + (size_t)r * K_TOTAL + c * 8);
    }
    const uint32_t b_s = abase + OFF_B + stage * B_BYTES;
#pragma unroll
    for (int it = 0; it < 2048 / NTH; it++) {
        int i = tid + it * NTH;
        int r = i >> 5, c = i & 31;     // rows 0..63
        uint32_t off = (uint32_t)(r * 512 + ((c * 16) ^ ((r & 7) << 4)));
        cp16(b_s + off, bsrc + (size_t)r * N_TOTAL + c * 8);
    }
}

// Half 2: B rows 64..127
__device__ __forceinline__ void load_tile_p2(uint32_t abase, int stage,
                                             const __half* __restrict__ bsrc,
                                             int tid) {
    const uint32_t b_s = abase + OFF_B + stage * B_BYTES;
#pragma unroll
    for (int it = 0; it < 2048 / NTH; it++) {
        int i = tid + it * NTH + 2048;
        int r = i >> 5, c = i & 31;     // rows 64..127
        uint32_t off = (uint32_t)(r * 512 + ((c * 16) ^ ((r & 7) << 4)));
        cp16(b_s + off, bsrc + (size_t)r * N_TOTAL + c * 8);
    }
}

__global__ void __launch_bounds__(NTH, 1)
gemm_kernel(const float* __restrict__ sc, const float* __restrict__ zz,
            const float* __restrict__ bb, float* __restrict__ out) {
    extern __shared__ char dsm[];
    const uint32_t raw = smem_u32(dsm);
    const uint32_t abase = (raw + 1023u) & ~1023u;
    char* smp = dsm + (abase - raw);

    const int tid = threadIdx.x;
    const int lane = tid & 31;
    const int wid = tid >> 5;
    const int warp_m = wid & 1;        // 2 warps over M (64 rows each)
    const int warp_n = wid >> 1;       // 4 warps over N (64 cols each)
    const int nt = blockIdx.x & 15;    // N fastest -> B stays L2-resident
    const int mt = blockIdx.x >> 4;
    const int m0 = mt * CTA_M;
    const int n0 = nt * CTA_N;

    // Incremental global source pointers
    const __half* aptr = g_xh + (size_t)m0 * K_TOTAL;
    const __half* bptr = g_wh + n0;

    // Prologue: tile 0 -> stage 0 (issue before anything else)
    load_tile_p1(abase, 0, aptr, bptr, tid);
    load_tile_p2(abase, 0, bptr, tid);
    asm volatile("cp.async.commit_group;" ::: "memory");
    aptr += K_TILE;
    bptr += (size_t)K_TILE * N_TOTAL;

    float* psc = reinterpret_cast<float*>(smp + OFF_SC);
    float* pzz = reinterpret_cast<float*>(smp + OFF_ZZ);
    float* pbb = reinterpret_cast<float*>(smp + OFF_BB);
    if (tid < CTA_N) {
        psc[tid] = sc[n0 + tid];
        pzz[tid] = zz[n0 + tid];
        pbb[tid] = bb[n0 + tid];
    }

    // Per-thread ldmatrix address invariants
    const int la = lane & 15, lb = lane >> 4;
    const uint32_t axor = (uint32_t)((la & 7) << 4);
    uint32_t a_row[4];
#pragma unroll
    for (int m = 0; m < 4; m++)
        a_row[m] = (uint32_t)((warp_m * 64 + m * 16 + la) * 256);
    const uint32_t bxor = (uint32_t)((la & 7) << 4);
    const uint32_t b_la = (uint32_t)(la * 512);
    const uint32_t nb_base = (uint32_t)(warp_n * 128 + lb * 16);

    float acc[4][8][4];
#pragma unroll
    for (int m = 0; m < 4; m++)
#pragma unroll
        for (int nf = 0; nf < 8; nf++)
#pragma unroll
            for (int v = 0; v < 4; v++) acc[m][nf][v] = 0.f;

    uint32_t A[2][4][4];   // [buf][m frag][reg]
    uint32_t Bv[2][4][4];  // [buf][16n group][reg]

    // Wait for tile 0; preload ks=0 fragments
    asm volatile("cp.async.wait_group 0;" ::: "memory");
    __syncthreads();
    {
        const uint32_t a_s = abase + OFF_A;
        const uint32_t b_s = abase + OFF_B;
#pragma unroll
        for (int m = 0; m < 4; m++)
            ldsm4(A[0][m], a_s + a_row[m] + (((uint32_t)(lb * 16)) ^ axor));
#pragma unroll
        for (int nn = 0; nn < 4; nn++)
            ldsm4t(Bv[0][nn], b_s + b_la + ((nb_base + nn * 32) ^ bxor));
    }

    for (int kt = 0; kt < NK; kt++) {
        const int stage = kt & 1;
        const uint32_t a_s = abase + OFF_A + stage * A_BYTES;
        const uint32_t b_s = abase + OFF_B + stage * B_BYTES;
        const bool more = (kt + 1 < NK);
        const __half* bcur = bptr;     // tile kt+1 B source (before increment)

        // Half 1 of tile kt+1 loads (A + B rows 0..63). Stage^1 is safe to
        // write: its readers finished before the ks=KCH-2 barrier of kt-1.
        if (more) {
            load_tile_p1(abase, stage ^ 1, aptr, bcur, tid);
            aptr += K_TILE;
        }
        asm volatile("cp.async.commit_group;" ::: "memory");

#pragma unroll
        for (int ks = 0; ks < KCH - 1; ks++) {
            const int cur = ks & 1, nxt = cur ^ 1;
            // Prefetch fragments for ks+1 (same stage)
#pragma unroll
            for (int m = 0; m < 4; m++)
                ldsm4(A[nxt][m], a_s + a_row[m] +
                      (((uint32_t)((ks + 1) * 32 + lb * 16)) ^ axor));
            const uint32_t b_row = (uint32_t)((ks + 1) * 16 * 512) + b_la;
#pragma unroll
            for (int nn = 0; nn < 4; nn++)
                ldsm4t(Bv[nxt][nn], b_s + b_row + ((nb_base + nn * 32) ^ bxor));

#pragma unroll
            for (int m = 0; m < 4; m++)
#pragma unroll
                for (int nf = 0; nf < 8; nf++)
                    mma16816(acc[m][nf], A[cur][m], Bv[cur][nf >> 1][(nf & 1) * 2],
                             Bv[cur][nf >> 1][(nf & 1) * 2 + 1]);

            if (ks == 2) {
                // Half 2 of tile kt+1 loads (B rows 64..127): spreads the
                // LSU/L2 burst; still ~4 chunks for the data to land.
                if (more) {
                    load_tile_p2(abase, stage ^ 1, bcur, tid);
                    bptr += (size_t)K_TILE * N_TOTAL;
                }
                asm volatile("cp.async.commit_group;" ::: "memory");
            }

            if (ks == KCH - 2) {
                // Tile kt+1 arrival. CORRECTNESS-PINNED position: after this
                // barrier no warp reads the current stage again, so iteration
                // kt+1 may safely overwrite it. Do NOT move earlier (R9 race).
                asm volatile("cp.async.wait_group 0;" ::: "memory");
                __syncthreads();
            }
        }

        // Cross-tile prefetch: ks=0 fragments of tile kt+1 from the other stage
        const int lastbuf = (KCH - 1) & 1;
        if (more) {
            const uint32_t a_n = abase + OFF_A + (stage ^ 1) * A_BYTES;
            const uint32_t b_n = abase + OFF_B + (stage ^ 1) * B_BYTES;
#pragma unroll
            for (int m = 0; m < 4; m++)
                ldsm4(A[lastbuf ^ 1][m], a_n + a_row[m] + (((uint32_t)(lb * 16)) ^ axor));
#pragma unroll
            for (int nn = 0; nn < 4; nn++)
                ldsm4t(Bv[lastbuf ^ 1][nn], b_n + b_la + ((nb_base + nn * 32) ^ bxor));
        }

        // Last mma chunk of tile kt (fragments in buf `lastbuf`)
#pragma unroll
        for (int m = 0; m < 4; m++)
#pragma unroll
            for (int nf = 0; nf < 8; nf++)
                mma16816(acc[m][nf], A[lastbuf][m], Bv[lastbuf][nf >> 1][(nf & 1) * 2],
                         Bv[lastbuf][nf >> 1][(nf & 1) * 2 + 1]);
        // Next iteration expects ks0 fragments in buf 0; KCH=8 -> lastbuf=1 ✓
    }

    // Epilogue: out = sc*acc - zz*rowsum + bias (streaming stores)
    const int r = lane >> 2;
    const int q2 = (lane & 3) * 2;
#pragma unroll
    for (int m = 0; m < 4; m++) {
        const int row = m0 + warp_m * 64 + m * 16 + r;
        const float rs0 = g_rowsum[row];
        const float rs1 = g_rowsum[row + 8];
        float* o0 = out + (size_t)row * N_TOTAL + n0;
        float* o1 = o0 + (size_t)8 * N_TOTAL;
#pragma unroll
        for (int nf = 0; nf < 8; nf++) {
            const int nl = warp_n * 64 + nf * 8 + q2;
            const float s0 = psc[nl], s1 = psc[nl + 1];
            const float z0 = pzz[nl], z1 = pzz[nl + 1];
            const float c0 = pbb[nl], c1 = pbb[nl + 1];
            float2 v0, v1;
            v0.x = fmaf(s0, acc[m][nf][0], fmaf(-z0, rs0, c0));
            v0.y = fmaf(s1, acc[m][nf][1], fmaf(-z1, rs0, c1));
            v1.x = fmaf(s0, acc[m][nf][2], fmaf(-z0, rs1, c0));
            v1.y = fmaf(s1, acc[m][nf][3], fmaf(-z1, rs1, c1));
            stcs2(o0 + nl, v0);
            stcs2(o1 + nl, v1);
        }
    }
}

// ----------------------------------------------------------------------------
// Launch
// ----------------------------------------------------------------------------
extern "C" void kernel_launch(void* const* d_in, const int* in_sizes, int n_in,
                              void* d_out, int out_size) {
    const float* x  = (const float*)d_in[0];
    const int*   qw = (const int*)d_in[1];
    const float* sc = (const float*)d_in[2];
    const float* zz = (const float*)d_in[3];
    const float* bb = (const float*)d_in[4];
    float* out = (float*)d_out;

    const int dq_blocks = (K_TOTAL / 8) * (N_TOTAL / 8) / 256;   // 1024
    prepass_kernel<<<M_TOTAL + dq_blocks, 256>>>(x, qw);

    cudaFuncSetAttribute(gemm_kernel, cudaFuncAttributeMaxDynamicSharedMemorySize, SMEM_BYTES);
    const int grid = (M_TOTAL / CTA_M) * (N_TOTAL / CTA_N);   // 64*16 = 1024
    gemm_kernel<<<grid, NTH, SMEM_BYTES>>>(sc, zz, bb, out);
}